// round 5
// baseline (speedup 1.0000x reference)
#include <cuda_runtime.h>
#include <math.h>
#include <stdint.h>

#define NN 32768
#define NE 65536

// ---------------- device scratch ----------------
__device__ float g_sum1[NN * 64];     // zeroed by node1 after consumption
__device__ float g_sum2[NN * 64];     // zeroed by node2 after consumption
__device__ float g_cnt [NN];          // zeroed by node2 after consumption
__device__ float g_h1  [NN * 64];
__device__ float g_h2  [NN * 64];
__device__ float g_he1 [NE * 64];     // relu(ea@W1a+b1a)
__device__ float g_he2 [NE * 64];     // relu(ea@W2a+b2a)
__device__ float g_Bt1 [4  * 4096];   // layer1 B chunks [c][k][n], tf32-rounded
__device__ float g_Bt2 [65 * 4096];   // layer2 B chunks [c][i][n], tf32-rounded

__device__ __forceinline__ float elu1(float v) { return v > 0.f ? v : expm1f(v); }

__device__ __forceinline__ float tf32r(float f) {
    uint32_t r;
    asm("cvt.rna.tf32.f32 %0, %1;" : "=r"(r) : "f"(f));
    return __uint_as_float(r);
}

__device__ __forceinline__ void mma8(float* c, const uint32_t* a, uint32_t b0, uint32_t b1) {
    asm volatile(
        "mma.sync.aligned.m16n8k8.row.col.f32.tf32.tf32.f32 "
        "{%0,%1,%2,%3}, {%4,%5,%6,%7}, {%8,%9}, {%0,%1,%2,%3};"
        : "+f"(c[0]), "+f"(c[1]), "+f"(c[2]), "+f"(c[3])
        : "r"(a[0]), "r"(a[1]), "r"(a[2]), "r"(a[3]), "r"(b0), "r"(b1));
}

#define CP_ASYNC16(dst_u32, src_ptr) \
    asm volatile("cp.async.cg.shared.global [%0], [%1], 16;" :: "r"(dst_u32), "l"(src_ptr))
#define CP_COMMIT()   asm volatile("cp.async.commit_group;")
#define CP_WAIT(n)    asm volatile("cp.async.wait_group %0;" :: "n"(n))

// ---------------- fused prep: he + btprep2 + btprep1 + cnt ----------------
// g_cnt is zero at entry: zero-initialized at load, re-zeroed by node2 each call.
__global__ __launch_bounds__(256) void prep_kernel(
    const int* __restrict__ ei, const float* __restrict__ ea,
    const float* __restrict__ W1a, const float* __restrict__ b1a,
    const float* __restrict__ W2a, const float* __restrict__ b2a,
    const float* __restrict__ W1b, const float* __restrict__ b1b,
    const float* __restrict__ W2b, const float* __restrict__ b2b)
{
    int b = blockIdx.x, t = threadIdx.x;
    if (b < 16384) {                                    // he: NE*64 threads
        int idx = b * 256 + t;
        int e = idx >> 6, c = idx & 63;
        float a0 = __ldg(&ea[e * 3]), a1 = __ldg(&ea[e * 3 + 1]), a2 = __ldg(&ea[e * 3 + 2]);
        float h1 = b1a[c] + a0 * W1a[c] + a1 * W1a[64 + c] + a2 * W1a[128 + c];
        float h2 = b2a[c] + a0 * W2a[c] + a1 * W2a[64 + c] + a2 * W2a[128 + c];
        g_he1[idx] = fmaxf(h1, 0.f);
        g_he2[idx] = fmaxf(h2, 0.f);
    } else if (b < 16384 + 1040) {                      // btprep2: 65*4096 threads
        int idx = (b - 16384) * 256 + t;
        int c = idx >> 12, r = idx & 4095;
        float v = (c < 64) ? W2b[c * 4096 + r] : b2b[r];
        g_Bt2[idx] = tf32r(v);
    } else if (b < 16384 + 1040 + 64) {                 // btprep1: 4*4096 threads
        int idx = (b - 16384 - 1040) * 256 + t;
        int c = idx >> 12, r = idx & 4095, k = r >> 6, n = r & 63;
        float v;
        if (c < 3) v = W1b[k * 192 + c * 64 + n];
        else       v = (k < 3) ? b1b[k * 64 + n] : 0.f;
        g_Bt1[idx] = tf32r(v);
    } else {                                            // cnt: NE threads
        int e = (b - 16384 - 1040 - 64) * 256 + t;
        atomicAdd(&g_cnt[ei[NE + e]], 1.f);
    }
}

// ---------------- bilinear inner compute ----------------
template<int JMAX, int VST>
__device__ __forceinline__ void compute_chunk(
    const float* __restrict__ B0,
    const float* __restrict__ Vbase,   // = V + (mb+g)*VST
    const float us[4], int q, int n0base,
    float (&cacc)[2][4][4])
{
    #pragma unroll
    for (int j = 0; j < JMAX; ++j) {
        int i0 = j * 8 + q, i1 = i0 + 4;
        float v0[4], v1[4];
        #pragma unroll
        for (int r = 0; r < 4; ++r) {
            const float* vp = Vbase + r * 8 * VST;
            v0[r] = vp[i0]; v1[r] = vp[i1];
        }
        uint32_t a[2][4];
        #pragma unroll
        for (int mt = 0; mt < 2; ++mt) {
            a[mt][0] = __float_as_uint(us[mt * 2]     * v0[mt * 2]);
            a[mt][1] = __float_as_uint(us[mt * 2 + 1] * v0[mt * 2 + 1]);
            a[mt][2] = __float_as_uint(us[mt * 2]     * v1[mt * 2]);
            a[mt][3] = __float_as_uint(us[mt * 2 + 1] * v1[mt * 2 + 1]);
        }
        #pragma unroll
        for (int nt = 0; nt < 4; ++nt) {
            int n0 = n0base + nt * 8;
            uint32_t b0 = __float_as_uint(B0[i0 * 68 + n0]);
            uint32_t b1 = __float_as_uint(B0[i1 * 68 + n0]);
            mma8(cacc[0][nt], a[0], b0, b1);
            mma8(cacc[1][nt], a[1], b0, b1);
        }
    }
}

// ---------------- bilinear message GEMM via mma.sync tf32 ----------------
// D[m=edge 0..127][n=0..63] = sum over outer steps s of u[m,s] * (v[m,:] . B_s[:,n])
// LAYER2: u = he2[e] (+1 bias), v = h1[src]; S = 65
// LAYER1: u = x[src] (+1 bias), v = he1[e] (bias inner = x); S = 4
template<int LAYER>
__global__ __launch_bounds__(256, 2) void bilinear_kernel(const int* __restrict__ ei,
                                                          const float* __restrict__ x)
{
    constexpr int S = (LAYER == 1) ? 4 : 65;
    const float* Bt   = (LAYER == 1) ? g_Bt1  : g_Bt2;
    float*       osum = (LAYER == 1) ? g_sum1 : g_sum2;

    extern __shared__ float sm[];
    float* U  = sm;                  // [128][68]
    float* V  = U  + 128 * 68;       // [128][68]
    float* VB = V  + 128 * 68;       // [128][12] (layer1 tail)
    float* Bs = VB + 128 * 12;       // [2][64*68]
    int*  srcs = (int*)(Bs + 2 * 64 * 68);   // [128]
    int*  dsts = srcs + 128;                  // [128]

    int t  = threadIdx.x;
    int e0 = blockIdx.x * 128;
    if (t < 128) { srcs[t] = ei[e0 + t]; dsts[t] = ei[NE + e0 + t]; }

    // prefetch B chunk 0 into buffer 0 (no dependency on srcs)
    #pragma unroll
    for (int j = 0; j < 4; ++j) {
        int fi = t * 4 + j, row = fi >> 4, c4 = fi & 15;
        uint32_t d = (uint32_t)__cvta_generic_to_shared(Bs + row * 68 + c4 * 4);
        CP_ASYNC16(d, Bt + fi * 4);
    }
    CP_COMMIT();
    __syncthreads();

    // load V (and U for layer2), tf32-rounded
    for (int idx = t; idx < 128 * 16; idx += 256) {
        int m = idx >> 4, q4 = idx & 15;
        const float* vsrc = (LAYER == 1) ? (g_he1 + (e0 + m) * 64) : (g_h1 + srcs[m] * 64);
        float4 vv = __ldg((const float4*)vsrc + q4);
        vv.x = tf32r(vv.x); vv.y = tf32r(vv.y); vv.z = tf32r(vv.z); vv.w = tf32r(vv.w);
        *(float4*)(V + m * 68 + q4 * 4) = vv;
        if (LAYER == 2) {
            float4 uu = __ldg((const float4*)(g_he2 + (e0 + m) * 64) + q4);
            uu.x = tf32r(uu.x); uu.y = tf32r(uu.y); uu.z = tf32r(uu.z); uu.w = tf32r(uu.w);
            *(float4*)(U + m * 68 + q4 * 4) = uu;
        }
    }
    if (t < 128) {
        if (LAYER == 2) {
            U[t * 68 + 64] = 1.f;
        } else {
            const float* xp = x + srcs[t] * 3;
            float x0 = tf32r(__ldg(xp)), x1 = tf32r(__ldg(xp + 1)), x2 = tf32r(__ldg(xp + 2));
            U[t * 68 + 0] = x0; U[t * 68 + 1] = x1; U[t * 68 + 2] = x2; U[t * 68 + 3] = 1.f;
            VB[t * 12 + 0] = x0; VB[t * 12 + 1] = x1; VB[t * 12 + 2] = x2;
            #pragma unroll
            for (int k = 3; k < 8; ++k) VB[t * 12 + k] = 0.f;
        }
    }

    int lane = t & 31, wid = t >> 5;
    int g = lane >> 2, q = lane & 3;
    int wm = wid >> 1, wn = wid & 1;
    int mb = wm * 32;
    int n0base = wn * 32 + g;
    const float* Ubase = U + (mb + g) * 68;
    const float* Vbase = V + (mb + g) * 68;
    const float* VBbase = VB + (mb + g) * 12;

    float cacc[2][4][4];
    #pragma unroll
    for (int a = 0; a < 2; ++a)
        #pragma unroll
        for (int b2 = 0; b2 < 4; ++b2)
            #pragma unroll
            for (int cx = 0; cx < 4; ++cx) cacc[a][b2][cx] = 0.f;

    for (int s = 0; s < S; ++s) {
        const float* B0 = Bs + (s & 1) * 4352;
        if (s + 1 < S) {
            float* Bn = Bs + ((s + 1) & 1) * 4352;
            const float* gsrc = Bt + (s + 1) * 4096;
            #pragma unroll
            for (int j = 0; j < 4; ++j) {
                int fi = t * 4 + j, row = fi >> 4, c4 = fi & 15;
                uint32_t d = (uint32_t)__cvta_generic_to_shared(Bn + row * 68 + c4 * 4);
                CP_ASYNC16(d, gsrc + fi * 4);
            }
            CP_COMMIT();
            CP_WAIT(1);
        } else {
            CP_WAIT(0);
        }
        __syncthreads();

        float us[4];
        #pragma unroll
        for (int r = 0; r < 4; ++r) us[r] = Ubase[r * 8 * 68 + s];

        if (LAYER == 2 || s < 3)
            compute_chunk<8, 68>(B0, Vbase, us, q, n0base, cacc);
        else
            compute_chunk<1, 12>(B0, VBbase, us, q, n0base, cacc);

        __syncthreads();
    }

    // epilogue: scatter-add C fragments
    #pragma unroll
    for (int mt = 0; mt < 2; ++mt) {
        #pragma unroll
        for (int half = 0; half < 2; ++half) {
            int m = mb + mt * 16 + half * 8 + g;
            float* op = osum + dsts[m] * 64 + wn * 32 + 2 * q;
            #pragma unroll
            for (int nt = 0; nt < 4; ++nt) {
                atomicAdd(op + nt * 8,     cacc[mt][nt][half * 2 + 0]);
                atomicAdd(op + nt * 8 + 1, cacc[mt][nt][half * 2 + 1]);
            }
        }
    }
}

// ---------------- layer 1 node combine (self-cleaning g_sum1) ----------------
__global__ void node1_kernel(const float* __restrict__ x,
                             const float* __restrict__ root1,
                             const float* __restrict__ bias1)
{
    int idx = blockIdx.x * blockDim.x + threadIdx.x;   // NN*64 threads
    int n = idx >> 6, o = idx & 63;
    float c = fmaxf(g_cnt[n], 1.f);
    float ssum = g_sum1[idx];
    g_sum1[idx] = 0.f;                                 // reset for next replay
    float v = ssum / c + bias1[o]
            + x[n * 3 + 0] * root1[o]
            + x[n * 3 + 1] * root1[64 + o]
            + x[n * 3 + 2] * root1[128 + o];
    g_h1[idx] = elu1(v);
}

// ---------------- layer 2 node combine (self-cleaning g_sum2, g_cnt) ----------------
__global__ __launch_bounds__(256) void node2_kernel(
    const float* __restrict__ root2, const float* __restrict__ bias2)
{
    __shared__ float hs[4][64];
    int nb = blockIdx.x * 4;
    int t = threadIdx.x;
    int ln = t >> 6, o = t & 63;
    hs[ln][o] = g_h1[(nb + ln) * 64 + o];
    __syncthreads();
    int n = nb + ln;
    float acc = bias2[o];
    #pragma unroll 8
    for (int i = 0; i < 64; ++i)
        acc = fmaf(hs[ln][i], __ldg(&root2[i * 64 + o]), acc);
    float c = fmaxf(g_cnt[n], 1.f);
    float ssum = g_sum2[n * 64 + o];
    g_sum2[n * 64 + o] = 0.f;                          // reset for next replay
    acc += ssum / c;
    g_h2[n * 64 + o] = elu1(acc);
    __syncthreads();                                   // all g_cnt reads done
    if (o == 0) g_cnt[n] = 0.f;                        // reset for next replay
}

// ---------------- final FC ----------------
__global__ __launch_bounds__(256) void fc_kernel(
    const float* __restrict__ Wf, const float* __restrict__ bf,
    float* __restrict__ out)
{
    __shared__ float hs[2][64];
    int nb = blockIdx.x * 2;
    int t = threadIdx.x;
    int ln = t >> 7, o = t & 127;
    if (o < 64) hs[ln][o] = g_h2[(nb + ln) * 64 + o];
    __syncthreads();
    float acc = bf[o];
    #pragma unroll 8
    for (int i = 0; i < 64; ++i)
        acc = fmaf(hs[ln][i], __ldg(&Wf[i * 128 + o]), acc);
    out[(nb + ln) * 128 + o] = elu1(acc);
}

// ---------------- launch ----------------
#define SM_BYTES ((128*68*2 + 128*12 + 2*64*68) * 4 + 256 * 4)

extern "C" void kernel_launch(void* const* d_in, const int* in_sizes, int n_in,
                              void* d_out, int out_size)
{
    const float* x     = (const float*)d_in[0];
    const int*   ei    = (const int*)d_in[1];
    const float* ea    = (const float*)d_in[2];
    const float* W1a   = (const float*)d_in[3];
    const float* b1a   = (const float*)d_in[4];
    const float* W1b   = (const float*)d_in[5];
    const float* b1b   = (const float*)d_in[6];
    const float* root1 = (const float*)d_in[7];
    const float* bias1 = (const float*)d_in[8];
    const float* W2a   = (const float*)d_in[9];
    const float* b2a   = (const float*)d_in[10];
    const float* W2b   = (const float*)d_in[11];
    const float* b2b   = (const float*)d_in[12];
    const float* root2 = (const float*)d_in[13];
    const float* bias2 = (const float*)d_in[14];
    const float* Wf    = (const float*)d_in[15];
    const float* bf    = (const float*)d_in[16];
    float*       out   = (float*)d_out;

    static int attr_done = 0;
    if (!attr_done) {
        cudaFuncSetAttribute(bilinear_kernel<1>, cudaFuncAttributeMaxDynamicSharedMemorySize, SM_BYTES);
        cudaFuncSetAttribute(bilinear_kernel<2>, cudaFuncAttributeMaxDynamicSharedMemorySize, SM_BYTES);
        attr_done = 1;
    }

    prep_kernel<<<16384 + 1040 + 64 + 256, 256>>>(ei, ea, W1a, b1a, W2a, b2a,
                                                  W1b, b1b, W2b, b2b);
    bilinear_kernel<1><<<NE / 128, 256, SM_BYTES>>>(ei, x);
    node1_kernel<<<NN * 64 / 256, 256>>>(x, root1, bias1);
    bilinear_kernel<2><<<NE / 128, 256, SM_BYTES>>>(ei, x);
    node2_kernel<<<NN / 4, 256>>>(root2, bias2);
    fc_kernel<<<NN / 2, 256>>>(Wf, bf, out);
}

// round 6
// speedup vs baseline: 1.1183x; 1.1183x over previous
#include <cuda_runtime.h>
#include <math.h>
#include <stdint.h>

#define NN 32768
#define NE 65536

// ---------------- device scratch ----------------
__device__ float g_sum1[NN * 64];     // zeroed by node1 after consumption
__device__ float g_sum2[NN * 64];     // zeroed by node2 after consumption
__device__ float g_cnt [NN];          // zeroed by node2 after consumption
__device__ float g_h1  [NN * 64];
__device__ float g_h2  [NN * 64];
__device__ float g_he1 [NE * 64];     // relu(ea@W1a+b1a)
__device__ float g_he2 [NE * 64];     // relu(ea@W2a+b2a)
__device__ float g_Bt1 [4  * 4096];   // layer1 B chunks [c][k][n], tf32-rounded
__device__ float g_Bt2 [65 * 4096];   // layer2 B chunks [c][i][n], tf32-rounded

__device__ __forceinline__ float elu1(float v) { return v > 0.f ? v : expm1f(v); }

__device__ __forceinline__ float tf32r(float f) {
    uint32_t r;
    asm("cvt.rna.tf32.f32 %0, %1;" : "=r"(r) : "f"(f));
    return __uint_as_float(r);
}

__device__ __forceinline__ void mma8(float* c, const uint32_t* a, uint32_t b0, uint32_t b1) {
    asm volatile(
        "mma.sync.aligned.m16n8k8.row.col.f32.tf32.tf32.f32 "
        "{%0,%1,%2,%3}, {%4,%5,%6,%7}, {%8,%9}, {%0,%1,%2,%3};"
        : "+f"(c[0]), "+f"(c[1]), "+f"(c[2]), "+f"(c[3])
        : "r"(a[0]), "r"(a[1]), "r"(a[2]), "r"(a[3]), "r"(b0), "r"(b1));
}

#define CP_ASYNC16(dst_u32, src_ptr) \
    asm volatile("cp.async.cg.shared.global [%0], [%1], 16;" :: "r"(dst_u32), "l"(src_ptr))
#define CP_COMMIT()   asm volatile("cp.async.commit_group;")
#define CP_WAIT(n)    asm volatile("cp.async.wait_group %0;" :: "n"(n))

// ---------------- fused prep: he + btprep2 + btprep1 + cnt ----------------
__global__ __launch_bounds__(256) void prep_kernel(
    const int* __restrict__ ei, const float* __restrict__ ea,
    const float* __restrict__ W1a, const float* __restrict__ b1a,
    const float* __restrict__ W2a, const float* __restrict__ b2a,
    const float* __restrict__ W1b, const float* __restrict__ b1b,
    const float* __restrict__ W2b, const float* __restrict__ b2b)
{
    int b = blockIdx.x, t = threadIdx.x;
    if (b < 16384) {                                    // he: NE*64 threads
        int idx = b * 256 + t;
        int e = idx >> 6, c = idx & 63;
        float a0 = __ldg(&ea[e * 3]), a1 = __ldg(&ea[e * 3 + 1]), a2 = __ldg(&ea[e * 3 + 2]);
        float h1 = b1a[c] + a0 * W1a[c] + a1 * W1a[64 + c] + a2 * W1a[128 + c];
        float h2 = b2a[c] + a0 * W2a[c] + a1 * W2a[64 + c] + a2 * W2a[128 + c];
        g_he1[idx] = fmaxf(h1, 0.f);
        g_he2[idx] = fmaxf(h2, 0.f);
    } else if (b < 16384 + 1040) {                      // btprep2: 65*4096 threads
        int idx = (b - 16384) * 256 + t;
        int c = idx >> 12, r = idx & 4095;
        float v = (c < 64) ? W2b[c * 4096 + r] : b2b[r];
        g_Bt2[idx] = tf32r(v);
    } else if (b < 16384 + 1040 + 64) {                 // btprep1: 4*4096 threads
        int idx = (b - 16384 - 1040) * 256 + t;
        int c = idx >> 12, r = idx & 4095, k = r >> 6, n = r & 63;
        float v;
        if (c < 3) v = W1b[k * 192 + c * 64 + n];
        else       v = (k < 3) ? b1b[k * 64 + n] : 0.f;
        g_Bt1[idx] = tf32r(v);
    } else {                                            // cnt: NE threads
        int e = (b - 16384 - 1040 - 64) * 256 + t;
        atomicAdd(&g_cnt[ei[NE + e]], 1.f);
    }
}

// ---------------- bilinear message GEMM via mma.sync tf32 ----------------
// D[m=edge 0..127][n=0..63] = sum over outer steps s of u[m,s] * (v[m,:] . B_s[:,n])
// Warp tile: 16m x 64n (8 warps cover 128 edges). V lives in REGISTERS (invariant
// across the s-loop); only B streams through smem (double-buffered cp.async).
// LAYER2: u = he2[e] (+1 bias), v = h1[src]; S = 65
// LAYER1: u = x[src] (+1 bias), v = he1[e] (tail chunk: v = x padded); S = 4
template<int LAYER>
__global__ __launch_bounds__(256, 2) void bilinear_kernel(const int* __restrict__ ei,
                                                          const float* __restrict__ x)
{
    constexpr int S = (LAYER == 1) ? 4 : 65;
    const float* Bt   = (LAYER == 1) ? g_Bt1  : g_Bt2;
    float*       osum = (LAYER == 1) ? g_sum1 : g_sum2;

    extern __shared__ float sm[];
    float* U  = sm;                       // [128][68]
    float* Bs = U + 128 * 68;             // [2][64][72]
    int*  srcs = (int*)(Bs + 2 * 64 * 72);   // [128]
    int*  dsts = srcs + 128;                  // [128]

    int t  = threadIdx.x;
    int e0 = blockIdx.x * 128;
    if (t < 128) { srcs[t] = ei[e0 + t]; dsts[t] = ei[NE + e0 + t]; }

    // prefetch B chunk 0 into buffer 0
    #pragma unroll
    for (int j = 0; j < 4; ++j) {
        int fi = t * 4 + j, row = fi >> 4, c4 = fi & 15;
        uint32_t d = (uint32_t)__cvta_generic_to_shared(Bs + row * 72 + c4 * 4);
        CP_ASYNC16(d, Bt + fi * 4);
    }
    CP_COMMIT();

    // fill U [128][68] (tf32-rounded)
    if (LAYER == 2) {
        for (int idx = t; idx < 128 * 16; idx += 256) {
            int m = idx >> 4, q4 = idx & 15;
            float4 uu = __ldg((const float4*)(g_he2 + (e0 + m) * 64) + q4);
            uu.x = tf32r(uu.x); uu.y = tf32r(uu.y); uu.z = tf32r(uu.z); uu.w = tf32r(uu.w);
            *(float4*)(U + m * 68 + q4 * 4) = uu;
        }
        if (t < 128) U[t * 68 + 64] = 1.f;
    } else {
        if (t < 128) {
            const float* xp = x + srcs[t] * 3;   // same-thread srcs write, no sync needed
            U[t * 68 + 0] = tf32r(__ldg(xp));
            U[t * 68 + 1] = tf32r(__ldg(xp + 1));
            U[t * 68 + 2] = tf32r(__ldg(xp + 2));
            U[t * 68 + 3] = 1.f;
        }
    }
    __syncthreads();   // srcs + U visible to all

    int lane = t & 31, wid = t >> 5;
    int g = lane >> 2, q = lane & 3;
    int mb = wid * 16;
    int row0 = mb + g, row1 = mb + g + 8;
    int s0 = srcs[row0], s1 = srcs[row1];

    // V -> registers (invariant over s): v[r][j][t] = V[row_r][q + 4t + 8j]
    float v[2][8][2];
    {
        const float* p0 = (LAYER == 2) ? (g_h1 + s0 * 64) : (g_he1 + (e0 + row0) * 64);
        const float* p1 = (LAYER == 2) ? (g_h1 + s1 * 64) : (g_he1 + (e0 + row1) * 64);
        #pragma unroll
        for (int j = 0; j < 8; ++j)
            #pragma unroll
            for (int tt = 0; tt < 2; ++tt) {
                int c = q + 4 * tt + 8 * j;
                v[0][j][tt] = tf32r(__ldg(p0 + c));
                v[1][j][tt] = tf32r(__ldg(p1 + c));
            }
    }
    float vt[2][2];   // layer1 tail-chunk A values (u=1, v=x padded)
    if (LAYER == 1) {
        #pragma unroll
        for (int tt = 0; tt < 2; ++tt) {
            int c = q + 4 * tt;
            vt[0][tt] = (c < 3) ? tf32r(__ldg(x + s0 * 3 + c)) : 0.f;
            vt[1][tt] = (c < 3) ? tf32r(__ldg(x + s1 * 3 + c)) : 0.f;
        }
    }

    float cacc[8][4];
    #pragma unroll
    for (int nt = 0; nt < 8; ++nt)
        #pragma unroll
        for (int cx = 0; cx < 4; ++cx) cacc[nt][cx] = 0.f;

    const float* Urow0 = U + row0 * 68;
    const float* Urow1 = U + row1 * 68;

    for (int s = 0; s < S; ++s) {
        const float* B0 = Bs + (s & 1) * 4608;
        if (s + 1 < S) {
            float* Bn = Bs + ((s + 1) & 1) * 4608;
            const float* gsrc = Bt + (s + 1) * 4096;
            #pragma unroll
            for (int j = 0; j < 4; ++j) {
                int fi = t * 4 + j, row = fi >> 4, c4 = fi & 15;
                uint32_t d = (uint32_t)__cvta_generic_to_shared(Bn + row * 72 + c4 * 4);
                CP_ASYNC16(d, gsrc + fi * 4);
            }
            CP_COMMIT();
            CP_WAIT(1);
        } else {
            CP_WAIT(0);
        }
        __syncthreads();

        if (LAYER == 1 && s == S - 1) {
            // tail: single k8 slice, A = x padded (u = 1)
            uint32_t A[4];
            A[0] = __float_as_uint(vt[0][0]);
            A[1] = __float_as_uint(vt[1][0]);
            A[2] = __float_as_uint(vt[0][1]);
            A[3] = __float_as_uint(vt[1][1]);
            const float* bp = B0 + q * 72 + g;
            #pragma unroll
            for (int nt = 0; nt < 8; ++nt) {
                uint32_t b0 = __float_as_uint(bp[nt * 8]);
                uint32_t b1 = __float_as_uint(bp[4 * 72 + nt * 8]);
                mma8(cacc[nt], A, b0, b1);
            }
        } else {
            float us0 = Urow0[s], us1 = Urow1[s];
            #pragma unroll
            for (int j = 0; j < 8; ++j) {
                uint32_t A[4];
                A[0] = __float_as_uint(us0 * v[0][j][0]);
                A[1] = __float_as_uint(us1 * v[1][j][0]);
                A[2] = __float_as_uint(us0 * v[0][j][1]);
                A[3] = __float_as_uint(us1 * v[1][j][1]);
                const float* bp = B0 + (j * 8 + q) * 72 + g;
                #pragma unroll
                for (int nt = 0; nt < 8; ++nt) {
                    uint32_t b0 = __float_as_uint(bp[nt * 8]);
                    uint32_t b1 = __float_as_uint(bp[4 * 72 + nt * 8]);
                    mma8(cacc[nt], A, b0, b1);
                }
            }
        }
        __syncthreads();
    }

    // epilogue: scatter-add C fragments (c0,c1 -> row0; c2,c3 -> row1)
    int d0 = dsts[row0], d1 = dsts[row1];
    float* o0 = osum + d0 * 64 + 2 * q;
    float* o1 = osum + d1 * 64 + 2 * q;
    #pragma unroll
    for (int nt = 0; nt < 8; ++nt) {
        atomicAdd(o0 + nt * 8,     cacc[nt][0]);
        atomicAdd(o0 + nt * 8 + 1, cacc[nt][1]);
        atomicAdd(o1 + nt * 8,     cacc[nt][2]);
        atomicAdd(o1 + nt * 8 + 1, cacc[nt][3]);
    }
}

// ---------------- layer 1 node combine (self-cleaning g_sum1) ----------------
__global__ void node1_kernel(const float* __restrict__ x,
                             const float* __restrict__ root1,
                             const float* __restrict__ bias1)
{
    int idx = blockIdx.x * blockDim.x + threadIdx.x;   // NN*64 threads
    int n = idx >> 6, o = idx & 63;
    float c = fmaxf(g_cnt[n], 1.f);
    float ssum = g_sum1[idx];
    g_sum1[idx] = 0.f;                                 // reset for next replay
    float v = ssum / c + bias1[o]
            + x[n * 3 + 0] * root1[o]
            + x[n * 3 + 1] * root1[64 + o]
            + x[n * 3 + 2] * root1[128 + o];
    g_h1[idx] = elu1(v);
}

// ---------------- layer 2 node combine (self-cleaning g_sum2, g_cnt) ----------------
__global__ __launch_bounds__(256) void node2_kernel(
    const float* __restrict__ root2, const float* __restrict__ bias2)
{
    __shared__ float hs[4][64];
    int nb = blockIdx.x * 4;
    int t = threadIdx.x;
    int ln = t >> 6, o = t & 63;
    hs[ln][o] = g_h1[(nb + ln) * 64 + o];
    __syncthreads();
    int n = nb + ln;
    float acc = bias2[o];
    #pragma unroll 8
    for (int i = 0; i < 64; ++i)
        acc = fmaf(hs[ln][i], __ldg(&root2[i * 64 + o]), acc);
    float c = fmaxf(g_cnt[n], 1.f);
    float ssum = g_sum2[n * 64 + o];
    g_sum2[n * 64 + o] = 0.f;                          // reset for next replay
    acc += ssum / c;
    g_h2[n * 64 + o] = elu1(acc);
    __syncthreads();                                   // all g_cnt reads done
    if (o == 0) g_cnt[n] = 0.f;                        // reset for next replay
}

// ---------------- final FC ----------------
__global__ __launch_bounds__(256) void fc_kernel(
    const float* __restrict__ Wf, const float* __restrict__ bf,
    float* __restrict__ out)
{
    __shared__ float hs[2][64];
    int nb = blockIdx.x * 2;
    int t = threadIdx.x;
    int ln = t >> 7, o = t & 127;
    if (o < 64) hs[ln][o] = g_h2[(nb + ln) * 64 + o];
    __syncthreads();
    float acc = bf[o];
    #pragma unroll 8
    for (int i = 0; i < 64; ++i)
        acc = fmaf(hs[ln][i], __ldg(&Wf[i * 128 + o]), acc);
    out[(nb + ln) * 128 + o] = elu1(acc);
}

// ---------------- launch ----------------
#define SM_BYTES ((128 * 68 + 2 * 64 * 72) * 4 + 256 * 4)

extern "C" void kernel_launch(void* const* d_in, const int* in_sizes, int n_in,
                              void* d_out, int out_size)
{
    const float* x     = (const float*)d_in[0];
    const int*   ei    = (const int*)d_in[1];
    const float* ea    = (const float*)d_in[2];
    const float* W1a   = (const float*)d_in[3];
    const float* b1a   = (const float*)d_in[4];
    const float* W1b   = (const float*)d_in[5];
    const float* b1b   = (const float*)d_in[6];
    const float* root1 = (const float*)d_in[7];
    const float* bias1 = (const float*)d_in[8];
    const float* W2a   = (const float*)d_in[9];
    const float* b2a   = (const float*)d_in[10];
    const float* W2b   = (const float*)d_in[11];
    const float* b2b   = (const float*)d_in[12];
    const float* root2 = (const float*)d_in[13];
    const float* bias2 = (const float*)d_in[14];
    const float* Wf    = (const float*)d_in[15];
    const float* bf    = (const float*)d_in[16];
    float*       out   = (float*)d_out;

    static int attr_done = 0;
    if (!attr_done) {
        cudaFuncSetAttribute(bilinear_kernel<1>, cudaFuncAttributeMaxDynamicSharedMemorySize, SM_BYTES);
        cudaFuncSetAttribute(bilinear_kernel<2>, cudaFuncAttributeMaxDynamicSharedMemorySize, SM_BYTES);
        attr_done = 1;
    }

    prep_kernel<<<16384 + 1040 + 64 + 256, 256>>>(ei, ea, W1a, b1a, W2a, b2a,
                                                  W1b, b1b, W2b, b2b);
    bilinear_kernel<1><<<NE / 128, 256, SM_BYTES>>>(ei, x);
    node1_kernel<<<NN * 64 / 256, 256>>>(x, root1, bias1);
    bilinear_kernel<2><<<NE / 128, 256, SM_BYTES>>>(ei, x);
    node2_kernel<<<NN / 4, 256>>>(root2, bias2);
    fc_kernel<<<NN / 2, 256>>>(Wf, bf, out);
}

// round 7
// speedup vs baseline: 1.1952x; 1.0688x over previous
#include <cuda_runtime.h>
#include <math.h>
#include <stdint.h>

#define NN 32768
#define NE 65536

// ---------------- device scratch ----------------
__device__ float g_sum1[NN * 64];     // zeroed by node1 after consumption
__device__ float g_sum2[NN * 64];     // zeroed by node2 after consumption
__device__ float g_cnt [NN];          // zeroed by node2 after consumption
__device__ float g_h1  [NN * 64];
__device__ float g_h2  [NN * 64];
__device__ float g_he1 [NE * 64];     // relu(ea@W1a+b1a)
__device__ float g_he2 [NE * 64];     // relu(ea@W2a+b2a)
__device__ float g_Bt1 [4  * 4096];   // layer1 B chunks [c][k][n^(8(k&3))], tf32
__device__ float g_Bt2 [65 * 4096];   // layer2 B chunks [c][i][n^(8(i&3))], tf32

__device__ __forceinline__ float elu1(float v) { return v > 0.f ? v : expm1f(v); }

__device__ __forceinline__ float tf32r(float f) {
    uint32_t r;
    asm("cvt.rna.tf32.f32 %0, %1;" : "=r"(r) : "f"(f));
    return __uint_as_float(r);
}

__device__ __forceinline__ void mma8(float* c, const uint32_t* a, uint32_t b0, uint32_t b1) {
    asm volatile(
        "mma.sync.aligned.m16n8k8.row.col.f32.tf32.tf32.f32 "
        "{%0,%1,%2,%3}, {%4,%5,%6,%7}, {%8,%9}, {%0,%1,%2,%3};"
        : "+f"(c[0]), "+f"(c[1]), "+f"(c[2]), "+f"(c[3])
        : "r"(a[0]), "r"(a[1]), "r"(a[2]), "r"(a[3]), "r"(b0), "r"(b1));
}

#define CP_ASYNC16(dst_u32, src_ptr) \
    asm volatile("cp.async.cg.shared.global [%0], [%1], 16;" :: "r"(dst_u32), "l"(src_ptr))
#define CP_COMMIT()   asm volatile("cp.async.commit_group;")
#define CP_WAIT(n)    asm volatile("cp.async.wait_group %0;" :: "n"(n))

// ---------------- fused prep: he + btprep2 + btprep1 + cnt ----------------
__global__ __launch_bounds__(256) void prep_kernel(
    const int* __restrict__ ei, const float* __restrict__ ea,
    const float* __restrict__ W1a, const float* __restrict__ b1a,
    const float* __restrict__ W2a, const float* __restrict__ b2a,
    const float* __restrict__ W1b, const float* __restrict__ b1b,
    const float* __restrict__ W2b, const float* __restrict__ b2b)
{
    int b = blockIdx.x, t = threadIdx.x;
    if (b < 16384) {                                    // he: NE*64 threads
        int idx = b * 256 + t;
        int e = idx >> 6, c = idx & 63;
        float a0 = __ldg(&ea[e * 3]), a1 = __ldg(&ea[e * 3 + 1]), a2 = __ldg(&ea[e * 3 + 2]);
        float h1 = b1a[c] + a0 * W1a[c] + a1 * W1a[64 + c] + a2 * W1a[128 + c];
        float h2 = b2a[c] + a0 * W2a[c] + a1 * W2a[64 + c] + a2 * W2a[128 + c];
        g_he1[idx] = fmaxf(h1, 0.f);
        g_he2[idx] = fmaxf(h2, 0.f);
    } else if (b < 16384 + 1040) {                      // btprep2: 65*4096 threads
        int idx = (b - 16384) * 256 + t;
        int c = idx >> 12, r = idx & 4095, i = r >> 6, n = r & 63;
        float v = (c < 64) ? W2b[c * 4096 + r] : b2b[r];
        g_Bt2[c * 4096 + i * 64 + (n ^ ((i & 3) << 3))] = tf32r(v);
    } else if (b < 16384 + 1040 + 64) {                 // btprep1: 4*4096 threads
        int idx = (b - 16384 - 1040) * 256 + t;
        int c = idx >> 12, r = idx & 4095, k = r >> 6, n = r & 63;
        float v;
        if (c < 3) v = W1b[k * 192 + c * 64 + n];
        else       v = (k < 3) ? b1b[k * 64 + n] : 0.f;
        g_Bt1[c * 4096 + k * 64 + (n ^ ((k & 3) << 3))] = tf32r(v);
    } else {                                            // cnt: NE threads
        int e = (b - 16384 - 1040 - 64) * 256 + t;
        atomicAdd(&g_cnt[ei[NE + e]], 1.f);
    }
}

// ---------------- bilinear message GEMM via mma.sync tf32 ----------------
// D[m=edge 0..127][n=0..63] = sum over outer steps s of u[m,s] * (v[m,:] . B_s[:,n])
// Warp tile: 32m x 32n (8 warps: 4 m-groups x 2 n-halves). V in registers (64/thr),
// B streams through 3 smem buffers (cp.async), ONE syncthreads per chunk.
// B smem layout XOR-swizzled (col n stored at n^(8*(i&3))) -> conflict-free LDS.
// LAYER2: u = he2[e] (+1 bias), v = h1[src]; S = 65
// LAYER1: u = x[src] (+1 bias), v = he1[e] (tail chunk: v = x padded); S = 4
template<int LAYER>
__global__ __launch_bounds__(256, 2) void bilinear_kernel(const int* __restrict__ ei,
                                                          const float* __restrict__ x)
{
    constexpr int S = (LAYER == 1) ? 4 : 65;
    const float* Bt   = (LAYER == 1) ? g_Bt1  : g_Bt2;
    float*       osum = (LAYER == 1) ? g_sum1 : g_sum2;

    extern __shared__ float sm[];
    float* U  = sm;                        // [128][68]
    float* Bs = U + 128 * 68;              // [3][4096]
    int*  srcs = (int*)(Bs + 3 * 4096);    // [128]
    int*  dsts = srcs + 128;               // [128]

    int t  = threadIdx.x;
    int e0 = blockIdx.x * 128;

    // prefetch chunk 0 into buf 0 (independent of everything)
    #pragma unroll
    for (int j = 0; j < 4; ++j) {
        int fi = t * 4 + j;
        uint32_t d = (uint32_t)__cvta_generic_to_shared(Bs + fi * 4);
        CP_ASYNC16(d, Bt + fi * 4);
    }
    CP_COMMIT();

    if (t < 128) { srcs[t] = ei[e0 + t]; dsts[t] = ei[NE + e0 + t]; }
    __syncthreads();   // srcs visible

    // fill U [128][68] (tf32-rounded); visible to loop via the per-chunk sync
    if (LAYER == 2) {
        for (int idx = t; idx < 128 * 16; idx += 256) {
            int m = idx >> 4, q4 = idx & 15;
            float4 uu = __ldg((const float4*)(g_he2 + (e0 + m) * 64) + q4);
            uu.x = tf32r(uu.x); uu.y = tf32r(uu.y); uu.z = tf32r(uu.z); uu.w = tf32r(uu.w);
            *(float4*)(U + m * 68 + q4 * 4) = uu;
        }
        if (t < 128) U[t * 68 + 64] = 1.f;
    } else {
        if (t < 128) {
            const float* xp = x + srcs[t] * 3;
            U[t * 68 + 0] = tf32r(__ldg(xp));
            U[t * 68 + 1] = tf32r(__ldg(xp + 1));
            U[t * 68 + 2] = tf32r(__ldg(xp + 2));
            U[t * 68 + 3] = 1.f;
        }
    }

    int lane = t & 31, wid = t >> 5;
    int g = lane >> 2, q = lane & 3;
    int wm = wid >> 1, wn = wid & 1;
    int mb = wm * 32;
    int rows[4] = { mb + g, mb + g + 8, mb + 16 + g, mb + 24 + g };

    // V -> registers (invariant over s): v[r][j][tt] = V[rows[r]][q + 4tt + 8j]
    float v[4][8][2];
    #pragma unroll
    for (int r = 0; r < 4; ++r) {
        const float* p = (LAYER == 2) ? (g_h1 + srcs[rows[r]] * 64)
                                      : (g_he1 + (e0 + rows[r]) * 64);
        #pragma unroll
        for (int j = 0; j < 8; ++j)
            #pragma unroll
            for (int tt = 0; tt < 2; ++tt)
                v[r][j][tt] = tf32r(__ldg(p + q + 4 * tt + 8 * j));
    }
    float vt[4][2];   // layer1 tail-chunk A values (u=1, v=x padded)
    if (LAYER == 1) {
        #pragma unroll
        for (int r = 0; r < 4; ++r) {
            int sv = srcs[rows[r]];
            #pragma unroll
            for (int tt = 0; tt < 2; ++tt) {
                int c = q + 4 * tt;
                vt[r][tt] = (c < 3) ? tf32r(__ldg(x + sv * 3 + c)) : 0.f;
            }
        }
    }

    float cacc[2][4][4];
    #pragma unroll
    for (int a = 0; a < 2; ++a)
        #pragma unroll
        for (int b2 = 0; b2 < 4; ++b2)
            #pragma unroll
            for (int cx = 0; cx < 4; ++cx) cacc[a][b2][cx] = 0.f;

    int bcol = wn * 32 + g;   // physical col = bcol + 8*(nt^q)

    for (int s = 0; s < S; ++s) {
        if (s + 1 < S) {
            float* Bn = Bs + ((s + 1) % 3) * 4096;
            const float* gsrc = Bt + (s + 1) * 4096;
            #pragma unroll
            for (int j = 0; j < 4; ++j) {
                int fi = t * 4 + j;
                uint32_t d = (uint32_t)__cvta_generic_to_shared(Bn + fi * 4);
                CP_ASYNC16(d, gsrc + fi * 4);
            }
            CP_COMMIT();
            CP_WAIT(1);
        } else {
            CP_WAIT(0);
        }
        __syncthreads();   // single barrier per chunk (3-buffer WAR distance = 2)
        const float* B0 = Bs + (s % 3) * 4096;

        if (LAYER == 1 && s == S - 1) {
            uint32_t A0[4], A1[4];
            A0[0] = __float_as_uint(vt[0][0]); A0[1] = __float_as_uint(vt[1][0]);
            A0[2] = __float_as_uint(vt[0][1]); A0[3] = __float_as_uint(vt[1][1]);
            A1[0] = __float_as_uint(vt[2][0]); A1[1] = __float_as_uint(vt[3][0]);
            A1[2] = __float_as_uint(vt[2][1]); A1[3] = __float_as_uint(vt[3][1]);
            const float* bp = B0 + q * 64 + bcol;
            #pragma unroll
            for (int nt = 0; nt < 4; ++nt) {
                uint32_t b0 = __float_as_uint(bp[8 * (nt ^ q)]);
                uint32_t b1 = __float_as_uint(bp[256 + 8 * (nt ^ q)]);
                mma8(cacc[0][nt], A0, b0, b1);
                mma8(cacc[1][nt], A1, b0, b1);
            }
        } else {
            float us0 = U[rows[0] * 68 + s];
            float us1 = U[rows[1] * 68 + s];
            float us2 = U[rows[2] * 68 + s];
            float us3 = U[rows[3] * 68 + s];
            #pragma unroll
            for (int j = 0; j < 8; ++j) {
                uint32_t A0[4], A1[4];
                A0[0] = __float_as_uint(us0 * v[0][j][0]);
                A0[1] = __float_as_uint(us1 * v[1][j][0]);
                A0[2] = __float_as_uint(us0 * v[0][j][1]);
                A0[3] = __float_as_uint(us1 * v[1][j][1]);
                A1[0] = __float_as_uint(us2 * v[2][j][0]);
                A1[1] = __float_as_uint(us3 * v[3][j][0]);
                A1[2] = __float_as_uint(us2 * v[2][j][1]);
                A1[3] = __float_as_uint(us3 * v[3][j][1]);
                const float* bp = B0 + (j * 8 + q) * 64 + bcol;
                #pragma unroll
                for (int nt = 0; nt < 4; ++nt) {
                    uint32_t b0 = __float_as_uint(bp[8 * (nt ^ q)]);
                    uint32_t b1 = __float_as_uint(bp[256 + 8 * (nt ^ q)]);
                    mma8(cacc[0][nt], A0, b0, b1);
                    mma8(cacc[1][nt], A1, b0, b1);
                }
            }
        }
    }

    // epilogue: scatter-add C fragments
    #pragma unroll
    for (int tile = 0; tile < 2; ++tile) {
        int dlo = dsts[rows[tile * 2]];
        int dhi = dsts[rows[tile * 2 + 1]];
        float* olo = osum + dlo * 64 + wn * 32 + 2 * q;
        float* ohi = osum + dhi * 64 + wn * 32 + 2 * q;
        #pragma unroll
        for (int nt = 0; nt < 4; ++nt) {
            atomicAdd(olo + nt * 8,     cacc[tile][nt][0]);
            atomicAdd(olo + nt * 8 + 1, cacc[tile][nt][1]);
            atomicAdd(ohi + nt * 8,     cacc[tile][nt][2]);
            atomicAdd(ohi + nt * 8 + 1, cacc[tile][nt][3]);
        }
    }
}

// ---------------- layer 1 node combine (self-cleaning g_sum1) ----------------
__global__ void node1_kernel(const float* __restrict__ x,
                             const float* __restrict__ root1,
                             const float* __restrict__ bias1)
{
    int idx = blockIdx.x * blockDim.x + threadIdx.x;   // NN*64 threads
    int n = idx >> 6, o = idx & 63;
    float c = fmaxf(g_cnt[n], 1.f);
    float ssum = g_sum1[idx];
    g_sum1[idx] = 0.f;                                 // reset for next replay
    float v = ssum / c + bias1[o]
            + x[n * 3 + 0] * root1[o]
            + x[n * 3 + 1] * root1[64 + o]
            + x[n * 3 + 2] * root1[128 + o];
    g_h1[idx] = elu1(v);
}

// ---------------- layer 2 node combine (self-cleaning g_sum2, g_cnt) ----------------
__global__ __launch_bounds__(256) void node2_kernel(
    const float* __restrict__ root2, const float* __restrict__ bias2)
{
    __shared__ float hs[4][64];
    int nb = blockIdx.x * 4;
    int t = threadIdx.x;
    int ln = t >> 6, o = t & 63;
    hs[ln][o] = g_h1[(nb + ln) * 64 + o];
    __syncthreads();
    int n = nb + ln;
    float acc = bias2[o];
    #pragma unroll 8
    for (int i = 0; i < 64; ++i)
        acc = fmaf(hs[ln][i], __ldg(&root2[i * 64 + o]), acc);
    float c = fmaxf(g_cnt[n], 1.f);
    float ssum = g_sum2[n * 64 + o];
    g_sum2[n * 64 + o] = 0.f;                          // reset for next replay
    acc += ssum / c;
    g_h2[n * 64 + o] = elu1(acc);
    __syncthreads();                                   // all g_cnt reads done
    if (o == 0) g_cnt[n] = 0.f;                        // reset for next replay
}

// ---------------- final FC ----------------
__global__ __launch_bounds__(256) void fc_kernel(
    const float* __restrict__ Wf, const float* __restrict__ bf,
    float* __restrict__ out)
{
    __shared__ float hs[2][64];
    int nb = blockIdx.x * 2;
    int t = threadIdx.x;
    int ln = t >> 7, o = t & 127;
    if (o < 64) hs[ln][o] = g_h2[(nb + ln) * 64 + o];
    __syncthreads();
    float acc = bf[o];
    #pragma unroll 8
    for (int i = 0; i < 64; ++i)
        acc = fmaf(hs[ln][i], __ldg(&Wf[i * 128 + o]), acc);
    out[(nb + ln) * 128 + o] = elu1(acc);
}

// ---------------- launch ----------------
#define SM_BYTES ((128 * 68 + 3 * 4096) * 4 + 256 * 4)

extern "C" void kernel_launch(void* const* d_in, const int* in_sizes, int n_in,
                              void* d_out, int out_size)
{
    const float* x     = (const float*)d_in[0];
    const int*   ei    = (const int*)d_in[1];
    const float* ea    = (const float*)d_in[2];
    const float* W1a   = (const float*)d_in[3];
    const float* b1a   = (const float*)d_in[4];
    const float* W1b   = (const float*)d_in[5];
    const float* b1b   = (const float*)d_in[6];
    const float* root1 = (const float*)d_in[7];
    const float* bias1 = (const float*)d_in[8];
    const float* W2a   = (const float*)d_in[9];
    const float* b2a   = (const float*)d_in[10];
    const float* W2b   = (const float*)d_in[11];
    const float* b2b   = (const float*)d_in[12];
    const float* root2 = (const float*)d_in[13];
    const float* bias2 = (const float*)d_in[14];
    const float* Wf    = (const float*)d_in[15];
    const float* bf    = (const float*)d_in[16];
    float*       out   = (float*)d_out;

    static int attr_done = 0;
    if (!attr_done) {
        cudaFuncSetAttribute(bilinear_kernel<1>, cudaFuncAttributeMaxDynamicSharedMemorySize, SM_BYTES);
        cudaFuncSetAttribute(bilinear_kernel<2>, cudaFuncAttributeMaxDynamicSharedMemorySize, SM_BYTES);
        attr_done = 1;
    }

    prep_kernel<<<16384 + 1040 + 64 + 256, 256>>>(ei, ea, W1a, b1a, W2a, b2a,
                                                  W1b, b1b, W2b, b2b);
    bilinear_kernel<1><<<NE / 128, 256, SM_BYTES>>>(ei, x);
    node1_kernel<<<NN * 64 / 256, 256>>>(x, root1, bias1);
    bilinear_kernel<2><<<NE / 128, 256, SM_BYTES>>>(ei, x);
    node2_kernel<<<NN / 4, 256>>>(root2, bias2);
    fc_kernel<<<NN / 2, 256>>>(Wf, bf, out);
}